// round 12
// baseline (speedup 1.0000x reference)
#include <cuda_runtime.h>
#include <cuda_fp16.h>
#include <stdint.h>

typedef unsigned long long ull;

#define D        128
#define BM       64
#define BK       32
#define MAXN     50000
#define MAXE     800000
#define SCAN_B   1024                       // nodes per scan block

// ---- scratch (__device__ globals; no allocations allowed) ----
__device__ __half g_suph[(size_t)MAXN * D];       // x @ W in fp16 (12.8 MB)
__device__ int    g_deg[MAXN];
__device__ int    g_start[MAXN + 1];
__device__ int    g_pos[MAXN];
__device__ ull    g_edge[MAXE];                   // packed (weight_bits<<32 | col)
__device__ int    g_bsum[(MAXN + SCAN_B - 1) / SCAN_B];

// ---------------------------------------------------------------------------
// packed f32x2 helpers (sm_103a FFMA2 — PTX-only, ptxas won't auto-fuse)
// ---------------------------------------------------------------------------
__device__ __forceinline__ void ffma2(ull& d, ull a, ull b) {
    asm("fma.rn.f32x2 %0, %1, %2, %0;" : "+l"(d) : "l"(a), "l"(b));
}
__device__ __forceinline__ ull pk2(float lo, float hi) {
    ull r; asm("mov.b64 %0, {%1, %2};" : "=l"(r) : "f"(lo), "f"(hi)); return r;
}
__device__ __forceinline__ void upk2(ull v, float& lo, float& hi) {
    asm("mov.b64 {%0, %1}, %2;" : "=f"(lo), "=f"(hi) : "l"(v));
}

// ---------------------------------------------------------------------------
// CSR build
// ---------------------------------------------------------------------------
// hist, x2 vectorized (E is even; tail guarded anyway)
__global__ void hist_kernel(const int2* __restrict__ er2, int E) {
    int i = blockIdx.x * blockDim.x + threadIdx.x;
    int e0 = i * 2;
    if (e0 >= E) return;
    int2 r = er2[i];
    atomicAdd(&g_deg[r.x], 1);
    if (e0 + 1 < E) atomicAdd(&g_deg[r.y], 1);
}

// K1: per-block exclusive scan of degrees; block totals to g_bsum
__global__ __launch_bounds__(SCAN_B) void scan1_kernel(int M) {
    __shared__ int sh[SCAN_B];
    int i = blockIdx.x * SCAN_B + threadIdx.x;
    int v = (i < M) ? g_deg[i] : 0;
    sh[threadIdx.x] = v;
    __syncthreads();
#pragma unroll
    for (int off = 1; off < SCAN_B; off <<= 1) {
        int t = (threadIdx.x >= off) ? sh[threadIdx.x - off] : 0;
        __syncthreads();
        sh[threadIdx.x] += t;
        __syncthreads();
    }
    if (i < M) g_start[i] = sh[threadIdx.x] - v;   // exclusive, block-local
    if (threadIdx.x == SCAN_B - 1) g_bsum[blockIdx.x] = sh[SCAN_B - 1];
}

// K2 (fused old scan2+scan3): every block re-derives the block-sum prefix
// in shared (nb<=64 serial adds — trivial), then applies its own offset.
__global__ __launch_bounds__(SCAN_B) void scan23_kernel(int nb, int M) {
    __shared__ int off_sh;
    __shared__ int sums[64];
    if (threadIdx.x < nb) sums[threadIdx.x] = g_bsum[threadIdx.x];
    __syncthreads();
    if (threadIdx.x == 0) {
        int run = 0;
        int b = (int)blockIdx.x;
        for (int k = 0; k < nb; ++k) {
            int t = sums[k];
            if (k == b) off_sh = run;
            run += t;
        }
        if (b == 0) g_start[M] = run;   // grand total
    }
    __syncthreads();
    int i = blockIdx.x * SCAN_B + threadIdx.x;
    if (i < M) {
        int s = g_start[i] + off_sh;
        g_start[i] = s;
        g_pos[i]   = s;
    }
}

// reorder edges into CSR slots, x2 vectorized
__global__ void reorder_kernel(const float2* __restrict__ ew2,
                               const int2* __restrict__ er2,
                               const int2* __restrict__ ec2, int E) {
    int i = blockIdx.x * blockDim.x + threadIdx.x;
    int e0 = i * 2;
    if (e0 >= E) return;
    int2   r = er2[i];
    int2   c = ec2[i];
    float2 w = ew2[i];
    int p0 = atomicAdd(&g_pos[r.x], 1);
    g_edge[p0] = ((ull)__float_as_uint(w.x) << 32) | (unsigned)c.x;
    if (e0 + 1 < E) {
        int p1 = atomicAdd(&g_pos[r.y], 1);
        g_edge[p1] = ((ull)__float_as_uint(w.y) << 32) | (unsigned)c.y;
    }
}

// ---------------------------------------------------------------------------
// GEMM: support = x @ W   (fp32 compute, packed f32x2; fp16 epilogue store)
// ---------------------------------------------------------------------------
__global__ __launch_bounds__(128) void gemm_kernel(
    const float* __restrict__ A, const float* __restrict__ W, int M)
{
    __shared__ float As[BM][BK + 4];
    __shared__ float Bs[BK][D];

    const int tid  = threadIdx.x;
    const int tx   = tid & 15;
    const int ty   = tid >> 4;
    const int row0 = blockIdx.x * BM;

    ull accP[8][4];
#pragma unroll
    for (int i = 0; i < 8; ++i)
#pragma unroll
        for (int j = 0; j < 4; ++j) accP[i][j] = 0ull;

    for (int kt = 0; kt < D; kt += BK) {
#pragma unroll
        for (int p = tid; p < BM * BK / 4; p += 128) {
            int m = p >> 3, k4 = p & 7;
            float4 v = make_float4(0.f, 0.f, 0.f, 0.f);
            int gr = row0 + m;
            if (gr < M) v = *(const float4*)&A[(size_t)gr * D + kt + k4 * 4];
            *(float4*)&As[m][k4 * 4] = v;
        }
#pragma unroll
        for (int p = tid; p < BK * D / 4; p += 128) {
            int kk = p >> 5, c4 = p & 31;
            *(float4*)&Bs[kk][c4 * 4] =
                *(const float4*)&W[(size_t)(kt + kk) * D + c4 * 4];
        }
        __syncthreads();

#pragma unroll
        for (int k = 0; k < BK; ++k) {
            ull aP[8];
#pragma unroll
            for (int i = 0; i < 8; ++i) {
                float a = As[ty * 8 + i][k];
                aP[i] = pk2(a, a);
            }
            const ull* bp = (const ull*)&Bs[k][tx * 8];
            ull bP[4] = {bp[0], bp[1], bp[2], bp[3]};
#pragma unroll
            for (int i = 0; i < 8; ++i)
#pragma unroll
                for (int j = 0; j < 4; ++j)
                    ffma2(accP[i][j], aP[i], bP[j]);
        }
        __syncthreads();
    }

#pragma unroll
    for (int i = 0; i < 8; ++i) {
        int gr = row0 + ty * 8 + i;
        if (gr < M) {
            float c0, c1, c2, c3, c4, c5, c6, c7;
            upk2(accP[i][0], c0, c1); upk2(accP[i][1], c2, c3);
            upk2(accP[i][2], c4, c5); upk2(accP[i][3], c6, c7);
            __half2 h0 = __floats2half2_rn(c0, c1);
            __half2 h1 = __floats2half2_rn(c2, c3);
            __half2 h2 = __floats2half2_rn(c4, c5);
            __half2 h3 = __floats2half2_rn(c6, c7);
            uint4 pack;
            pack.x = *(unsigned*)&h0; pack.y = *(unsigned*)&h1;
            pack.z = *(unsigned*)&h2; pack.w = *(unsigned*)&h3;
            *(uint4*)&g_suph[(size_t)gr * D + tx * 8] = pack;
        }
    }
}

// ---------------------------------------------------------------------------
// Gather: one warp per node, unroll-4 for MLP. Atomic-free. fp16 reads,
// fp32 accumulate. Lane i covers cols [4i, 4i+4).
// ---------------------------------------------------------------------------
__global__ __launch_bounds__(256) void gather_kernel(
    const float4* __restrict__ bias4, float4* __restrict__ out4, int M)
{
    int warp = (blockIdx.x * blockDim.x + threadIdx.x) >> 5;
    int lane = threadIdx.x & 31;
    if (warp >= M) return;

    int s = g_start[warp];
    int e = g_start[warp + 1];

    const uint2* suph = (const uint2*)g_suph;   // row = 32 uint2 (256 B)
    float4 acc = make_float4(0.f, 0.f, 0.f, 0.f);

#define EDGE_FMA(P)                                                          \
    {                                                                        \
        float w  = __uint_as_float((unsigned)((P) >> 32));                   \
        uint2 h  = __ldg(&suph[(size_t)(unsigned)(P) * 32 + lane]);          \
        float2 f01 = __half22float2(*(__half2*)&h.x);                        \
        float2 f23 = __half22float2(*(__half2*)&h.y);                        \
        acc.x = fmaf(f01.x, w, acc.x); acc.y = fmaf(f01.y, w, acc.y);        \
        acc.z = fmaf(f23.x, w, acc.z); acc.w = fmaf(f23.y, w, acc.w);        \
    }

    int i = s;
    for (; i + 3 < e; i += 4) {
        ull p0 = __ldg(&g_edge[i]),     p1 = __ldg(&g_edge[i + 1]);
        ull p2 = __ldg(&g_edge[i + 2]), p3 = __ldg(&g_edge[i + 3]);
        EDGE_FMA(p0); EDGE_FMA(p1); EDGE_FMA(p2); EDGE_FMA(p3);
    }
    for (; i < e; ++i) {
        ull p0 = __ldg(&g_edge[i]);
        EDGE_FMA(p0);
    }
#undef EDGE_FMA

    float4 b = bias4[lane];
    acc.x += b.x; acc.y += b.y; acc.z += b.z; acc.w += b.w;
    out4[(size_t)warp * (D / 4) + lane] = acc;
}

// ---------------------------------------------------------------------------
extern "C" void kernel_launch(void* const* d_in, const int* in_sizes, int n_in,
                              void* d_out, int out_size)
{
    const float* x      = (const float*)d_in[0];
    const float* weight = (const float*)d_in[1];
    const float* bias   = (const float*)d_in[2];
    const float* ew     = (const float*)d_in[3];
    const int*   er     = (const int*)d_in[4];
    const int*   ec     = (const int*)d_in[5];
    float*       out    = (float*)d_out;

    const int M  = in_sizes[0] / D;                // 50000
    const int E  = in_sizes[3];                    // 800000
    const int NB = (M + SCAN_B - 1) / SCAN_B;      // 49
    const int E2 = (E + 1) / 2;                    // vectorized edge count

    // fork: GEMM (independent of CSR build) runs on a side stream
    cudaStream_t sg;
    cudaEvent_t  ev_fork, ev_join;
    cudaStreamCreateWithFlags(&sg, cudaStreamNonBlocking);
    cudaEventCreateWithFlags(&ev_fork, cudaEventDisableTiming);
    cudaEventCreateWithFlags(&ev_join, cudaEventDisableTiming);

    cudaEventRecord(ev_fork, 0);
    cudaStreamWaitEvent(sg, ev_fork, 0);
    gemm_kernel<<<(M + BM - 1) / BM, 128, 0, sg>>>(x, weight, M);
    cudaEventRecord(ev_join, sg);

    // CSR build on the main (capture) stream
    {
        void* degp = nullptr;
        cudaGetSymbolAddress(&degp, g_deg);
        cudaMemsetAsync(degp, 0, (size_t)M * sizeof(int), 0);
    }
    hist_kernel<<<(E2 + 255) / 256, 256>>>((const int2*)er, E);
    scan1_kernel<<<NB, SCAN_B>>>(M);
    scan23_kernel<<<NB, SCAN_B>>>(NB, M);
    reorder_kernel<<<(E2 + 255) / 256, 256>>>(
        (const float2*)ew, (const int2*)er, (const int2*)ec, E);

    // join, then gather
    cudaStreamWaitEvent(0, ev_join, 0);
    {
        long long threads = (long long)M * 32;
        gather_kernel<<<(int)((threads + 255) / 256), 256>>>(
            (const float4*)bias, (float4*)out, M);
    }
}